// round 1
// baseline (speedup 1.0000x reference)
#include <cuda_runtime.h>
#include <cuda_bf16.h>

// LinearRationalSpline forward.
// inputs:  d_in[0] = inputs        [16384*64]        float32
//          d_in[1] = params_unnorm [16384*64, 63]    float32
// output:  d_out = concat(outputs, logabsdet) [2 * 16384*64] float32

#define KB 16                 // NUM_BINS
#define PPE 63                // params per element (4*K - 1)
#define TPB 128               // threads per block

__device__ __forceinline__ float softplus_f(float x) {
    // log1p(exp(x)) computed stably
    return fmaxf(x, 0.0f) + log1pf(__expf(-fabsf(x)));
}

__global__ __launch_bounds__(TPB)
void lrs_kernel(const float* __restrict__ inp,
                const float* __restrict__ par,
                float* __restrict__ out,
                int n)
{
    const float BOUND = 3.0f;
    const float MBW   = 0.001f;   // min bin width
    const float MBH   = 0.001f;   // min bin height
    const float MD    = 0.001f;   // min derivative
    const float EPSV  = 1e-6f;

    __shared__ float sp[TPB * PPE];   // 32256 B

    const int base_elem = blockIdx.x * TPB;
    const float* gsrc = par + (size_t)base_elem * PPE;

    // ---- Stage params for this block into shared (coalesced) ----
    if (base_elem + TPB <= n) {
        // Block-base byte offset = blockIdx * 32256, which is 16B aligned.
        const float4* g4 = reinterpret_cast<const float4*>(gsrc);
        float4* s4 = reinterpret_cast<float4*>(sp);
        #pragma unroll
        for (int i = threadIdx.x; i < (TPB * PPE) / 4; i += TPB)
            s4[i] = g4[i];
    } else {
        int rem = (n - base_elem) * PPE;
        for (int i = threadIdx.x; i < rem; i += TPB)
            sp[i] = gsrc[i];
    }
    __syncthreads();

    const int e = base_elem + threadIdx.x;
    if (e >= n) return;

    // Per-thread row in shared: stride 63 (odd) -> bank-conflict free.
    const float* p = sp + threadIdx.x * PPE;
    const float x = inp[e];

    // ---- softmax numerators for widths / heights ----
    float ew[KB], eh[KB];
    float sw = 0.0f, sh = 0.0f;
    #pragma unroll
    for (int i = 0; i < KB; i++) { float v = __expf(p[i]);      ew[i] = v; sw += v; }
    #pragma unroll
    for (int i = 0; i < KB; i++) { float v = __expf(p[KB + i]); eh[i] = v; sh += v; }

    // knots: knot_{i+1} = -BOUND + 6*( MBW*(i+1) + (1-16*MBW) * cum/sum ), knot_K forced to BOUND
    const float scw = __fdividef(6.0f * (1.0f - MBW * KB), sw);
    const float sch = __fdividef(6.0f * (1.0f - MBH * KB), sh);

    float cw = 0.0f, ch = 0.0f;
    #pragma unroll
    for (int i = 0; i < KB; i++) {
        cw += ew[i];
        ch += eh[i];
        float offw = -BOUND + 6.0f * MBW * (float)(i + 1);
        float offh = -BOUND + 6.0f * MBH * (float)(i + 1);
        // ew[i] now holds knot_{i+1} of widths, eh[i] knot_{i+1} of heights
        ew[i] = (i == KB - 1) ? BOUND : fmaf(cw, scw, offw);
        eh[i] = (i == KB - 1) ? BOUND : fmaf(ch, sch, offh);
    }

    // ---- bin search: idx = clip(sum_{i=0..16}[knot_i+eps <= x] - 1, 0, 15)
    // equals count over interior knots 1..15 (knot_0 handled by -1, knot_16 by clip)
    int idx = 0;
    #pragma unroll
    for (int i = 0; i < KB - 1; i++)
        idx += (ew[i] + EPSV <= x) ? 1 : 0;

    // ---- select bin edges via predicated unrolled scan (register arrays, static idx)
    float cwl = -BOUND, cwr = ew[0], chl = -BOUND, chr = eh[0];
    #pragma unroll
    for (int i = 1; i < KB; i++) {
        if (idx == i) { cwl = ew[i-1]; cwr = ew[i]; chl = eh[i-1]; chr = eh[i]; }
    }

    const float wsel = cwr - cwl;       // selected bin width
    const float hsel = chr - chl;       // selected bin height

    // ---- derivatives at the two surrounding knots (only 2 softplus needed)
    // der array = [0.999, MD + softplus(d_0..d_14), 0.999], select idx, idx+1
    float dl, dr;
    {
        float dls = MD + softplus_f(p[2*KB + idx - 1]);  // safe read even at idx==0 (lands in h region)
        float drs = MD + softplus_f(p[2*KB + idx]);      // safe read at idx==15 (lands in lam region)
        dl = (idx == 0)      ? (1.0f - MD) : dls;
        dr = (idx == KB - 1) ? (1.0f - MD) : drs;
    }

    // ---- lambda (only selected)
    float lamraw = p[3*KB - 1 + idx];
    float sig = __fdividef(1.0f, 1.0f + __expf(-lamraw));
    float lam = fmaf(0.95f, sig, 0.025f);    // (1-2*MIN_LAMBDA)*sig + MIN_LAMBDA

    // ---- rational-linear spline evaluation
    float wb  = sqrtf(__fdividef(dl, dr));
    float lwb = lam * wb;
    float wc  = __fdividef(fmaf(lam, dl, (wb - lwb) * dr) * wsel, hsel);

    float ya = chl;
    float yb = chr;                    // hsel + chl
    float l1 = 1.0f - lam;
    float yc = __fdividef(fmaf(lwb, yb, l1 * ya), l1 + lwb);

    float theta  = __fdividef(x - cwl, wsel);
    bool  ind    = theta <= lam;
    float ltheta = lam - theta;

    float wcyc      = wc * yc;
    float wcyctheta = wcyc * theta;
    float num = ind ? fmaf(ya, ltheta, wcyctheta)
                    : (wcyc - wcyctheta) - (wb * yb) * ltheta;
    float wctheta = wc * theta;
    float den = ind ? (wctheta + ltheta)
                    : (wc - wctheta) - wb * ltheta;

    float outv = __fdividef(num, den);

    float dnum = __fdividef(wc * (ind ? lam * (yc - ya) : (wb - lwb) * (yb - yc)), wsel);
    float lad  = __logf(dnum) - 2.0f * __logf(fabsf(den));

    bool outside = (x < -BOUND) || (x > BOUND);
    out[e]     = outside ? x    : outv;
    out[n + e] = outside ? 0.0f : lad;
}

extern "C" void kernel_launch(void* const* d_in, const int* in_sizes, int n_in,
                              void* d_out, int out_size) {
    const float* inp = (const float*)d_in[0];
    const float* par = (const float*)d_in[1];
    float* out = (float*)d_out;
    int n = in_sizes[0];                 // 16384*64 elements
    int grid = (n + TPB - 1) / TPB;
    lrs_kernel<<<grid, TPB>>>(inp, par, out, n);
}

// round 2
// speedup vs baseline: 1.2000x; 1.2000x over previous
#include <cuda_runtime.h>
#include <cuda_bf16.h>
#include <cstdint>

// LinearRationalSpline forward — persistent, cp.async double-buffered.
// inputs:  d_in[0] = inputs        [16384*64]        float32
//          d_in[1] = params_unnorm [16384*64, 63]    float32
// output:  d_out = concat(outputs, logabsdet) [2 * 16384*64] float32

#define KB  16                // NUM_BINS
#define PPE 63                // params per element (4*K - 1)
#define TPB 128               // threads per block
#define GRID_CTAS 444         // 148 SMs * 3 resident CTAs

// dynamic smem layout: pbuf[2][TPB*PPE] then xbuf[2][TPB]
#define SMEM_FLOATS (2 * TPB * PPE + 2 * TPB)
#define SMEM_BYTES  (SMEM_FLOATS * 4)   // 65536

__device__ __forceinline__ void cp16(uint32_t dst, const void* src) {
    asm volatile("cp.async.cg.shared.global [%0], [%1], 16;" :: "r"(dst), "l"(src));
}
__device__ __forceinline__ void cp4(uint32_t dst, const void* src) {
    asm volatile("cp.async.ca.shared.global [%0], [%1], 4;" :: "r"(dst), "l"(src));
}
__device__ __forceinline__ void cp_commit() {
    asm volatile("cp.async.commit_group;");
}
template <int N>
__device__ __forceinline__ void cp_wait() {
    asm volatile("cp.async.wait_group %0;" :: "n"(N));
}

__device__ __forceinline__ float softplus_f(float x) {
    return fmaxf(x, 0.0f) + log1pf(__expf(-fabsf(x)));
}

__device__ __forceinline__ void prefetch_tile(int tile, int n,
                                              const float* __restrict__ par,
                                              const float* __restrict__ inp,
                                              float* pb, float* xb)
{
    const int base = tile * TPB;
    const int t = threadIdx.x;
    uint32_t sp = (uint32_t)__cvta_generic_to_shared(pb);
    uint32_t sx = (uint32_t)__cvta_generic_to_shared(xb);
    if (base + TPB <= n) {
        // tile byte base = tile * 32256 -> 16B aligned
        const float4* g4 = reinterpret_cast<const float4*>(par + (size_t)base * PPE);
        #pragma unroll 4
        for (int i = t; i < (TPB * PPE) / 4; i += TPB)
            cp16(sp + i * 16, g4 + i);
        if (t < TPB / 4)
            cp16(sx + t * 16, reinterpret_cast<const float4*>(inp + base) + t);
    } else {
        int remw = (n - base) * PPE;
        const float* g = par + (size_t)base * PPE;
        for (int i = t; i < remw; i += TPB)
            cp4(sp + i * 4, g + i);
        if (t < n - base)
            cp4(sx + t * 4, inp + base + t);
    }
}

__global__ __launch_bounds__(TPB)
void lrs_kernel(const float* __restrict__ inp,
                const float* __restrict__ par,
                float* __restrict__ out,
                int n)
{
    const float BOUND = 3.0f;
    const float MBW   = 0.001f;
    const float MBH   = 0.001f;
    const float MD    = 0.001f;
    const float EPSV  = 1e-6f;

    extern __shared__ float smem[];
    float* pbuf0 = smem;
    float* pbuf1 = smem + TPB * PPE;
    float* xbuf0 = smem + 2 * TPB * PPE;
    float* xbuf1 = xbuf0 + TPB;

    const int ntiles = (n + TPB - 1) / TPB;
    int tile = blockIdx.x;
    if (tile >= ntiles) return;

    prefetch_tile(tile, n, par, inp, pbuf0, xbuf0);
    cp_commit();

    int cur = 0;
    for (; tile < ntiles; tile += gridDim.x) {
        int nxt = tile + gridDim.x;
        if (nxt < ntiles)
            prefetch_tile(nxt, n, par, inp, cur ? pbuf0 : pbuf1, cur ? xbuf0 : xbuf1);
        cp_commit();                // uniform group count even if empty
        cp_wait<1>();               // current tile's group done; next may be in flight
        __syncthreads();

        float* pb = cur ? pbuf1 : pbuf0;
        float* xb = cur ? xbuf1 : xbuf0;

        const int e = tile * TPB + threadIdx.x;
        if (e < n) {
            const float* p = pb + threadIdx.x * PPE;   // stride 63 -> bank-conflict free
            const float x = xb[threadIdx.x];

            // ---- softmax numerators for widths / heights ----
            float ew[KB], eh[KB];
            float sw = 0.0f, sh = 0.0f;
            #pragma unroll
            for (int i = 0; i < KB; i++) { float v = __expf(p[i]);      ew[i] = v; sw += v; }
            #pragma unroll
            for (int i = 0; i < KB; i++) { float v = __expf(p[KB + i]); eh[i] = v; sh += v; }

            const float scw = __fdividef(6.0f * (1.0f - MBW * KB), sw);
            const float sch = __fdividef(6.0f * (1.0f - MBH * KB), sh);

            float cw = 0.0f, ch = 0.0f;
            #pragma unroll
            for (int i = 0; i < KB; i++) {
                cw += ew[i];
                ch += eh[i];
                float offw = -BOUND + 6.0f * MBW * (float)(i + 1);
                float offh = -BOUND + 6.0f * MBH * (float)(i + 1);
                ew[i] = (i == KB - 1) ? BOUND : fmaf(cw, scw, offw);
                eh[i] = (i == KB - 1) ? BOUND : fmaf(ch, sch, offh);
            }

            // ---- bin search over interior knots ----
            int idx = 0;
            #pragma unroll
            for (int i = 0; i < KB - 1; i++)
                idx += (ew[i] + EPSV <= x) ? 1 : 0;

            // ---- select bin edges (predicated unrolled, static indices) ----
            float cwl = -BOUND, cwr = ew[0], chl = -BOUND, chr = eh[0];
            #pragma unroll
            for (int i = 1; i < KB; i++) {
                if (idx == i) { cwl = ew[i-1]; cwr = ew[i]; chl = eh[i-1]; chr = eh[i]; }
            }

            const float wsel = cwr - cwl;
            const float hsel = chr - chl;

            // ---- derivatives at surrounding knots (2 softplus only) ----
            float dl, dr;
            {
                float dls = MD + softplus_f(p[2*KB + idx - 1]);
                float drs = MD + softplus_f(p[2*KB + idx]);
                dl = (idx == 0)      ? (1.0f - MD) : dls;
                dr = (idx == KB - 1) ? (1.0f - MD) : drs;
            }

            // ---- lambda (selected only) ----
            float lamraw = p[3*KB - 1 + idx];
            float sig = __fdividef(1.0f, 1.0f + __expf(-lamraw));
            float lam = fmaf(0.95f, sig, 0.025f);

            // ---- rational-linear spline ----
            float wb  = sqrtf(__fdividef(dl, dr));
            float lwb = lam * wb;
            float wc  = __fdividef(fmaf(lam, dl, (wb - lwb) * dr) * wsel, hsel);

            float ya = chl;
            float yb = chr;
            float l1 = 1.0f - lam;
            float yc = __fdividef(fmaf(lwb, yb, l1 * ya), l1 + lwb);

            float theta  = __fdividef(x - cwl, wsel);
            bool  ind    = theta <= lam;
            float ltheta = lam - theta;

            float wcyc      = wc * yc;
            float wcyctheta = wcyc * theta;
            float num = ind ? fmaf(ya, ltheta, wcyctheta)
                            : (wcyc - wcyctheta) - (wb * yb) * ltheta;
            float wctheta = wc * theta;
            float den = ind ? (wctheta + ltheta)
                            : (wc - wctheta) - wb * ltheta;

            float outv = __fdividef(num, den);

            float dnum = __fdividef(wc * (ind ? lam * (yc - ya) : (wb - lwb) * (yb - yc)), wsel);
            float lad  = __logf(dnum) - 2.0f * __logf(fabsf(den));

            bool outside = (x < -BOUND) || (x > BOUND);
            out[e]     = outside ? x    : outv;
            out[n + e] = outside ? 0.0f : lad;
        }

        __syncthreads();   // all reads of this buffer done before it becomes prefetch target
        cur ^= 1;
    }
}

extern "C" void kernel_launch(void* const* d_in, const int* in_sizes, int n_in,
                              void* d_out, int out_size) {
    const float* inp = (const float*)d_in[0];
    const float* par = (const float*)d_in[1];
    float* out = (float*)d_out;
    int n = in_sizes[0];

    cudaFuncSetAttribute(lrs_kernel, cudaFuncAttributeMaxDynamicSharedMemorySize, SMEM_BYTES);

    int ntiles = (n + TPB - 1) / TPB;
    int grid = GRID_CTAS < ntiles ? GRID_CTAS : ntiles;
    lrs_kernel<<<grid, TPB, SMEM_BYTES>>>(inp, par, out, n);
}